// round 16
// baseline (speedup 1.0000x reference)
#include <cuda_runtime.h>
#include <cuda_bf16.h>
#include <cstdint>
#include <math.h>

// ---------------------------------------------------------------------------
// CDConv: offset-conv(3x3,128->256, bf16-split mma.sync)+tanh ->
//         fused depthwise+grid_sample(->bf16 hi/lo planes) ->
//         pointwise(1x1, bf16-split mma)
// B=16, C=128, H=W=112, OUTC=256
// R16 = R15 + pwconv processes 2 pixel tiles per CTA (8 chained pipeline
//       stages, amortized fill/drain) + dwgs at 1024 threads.
// ---------------------------------------------------------------------------

#define BB   16
#define CC   128
#define HH   112
#define WW   112
#define HW   12544
#define MOFF 256
#define NSTG 36               // offset conv: K=1152 / 32
#define NSTG_PW 4             // pointwise:  K=128 / 32

#define NPIX  (BB * CC * HW)
#define GUARD 128

__device__ float    g_offset[BB * MOFF * HW];
__device__ uint32_t g_xpk[NPIX + 2 * GUARD];                 // {bf16 hi | lo<<16}
__device__ unsigned short g_shi[NPIX];                       // sampled hi plane
__device__ unsigned short g_slo[NPIX];                       // sampled lo plane
__device__ unsigned short g_Aoffbf[NSTG * 2 * 2 * 128 * 32]; // [t][mh][split][m][k]
__device__ unsigned short g_Apwbf[NSTG_PW * 2 * 2 * 128 * 32];

// ======================= helpers ==========================================
__device__ __forceinline__ uint32_t smem_u32(const void* p) {
    uint32_t a;
    asm("{ .reg .u64 t; cvta.to.shared.u64 t, %1; cvt.u32.u64 %0, t; }"
        : "=r"(a) : "l"(p));
    return a;
}
__device__ __forceinline__ void cp16(uint32_t dst, const void* src) {
    asm volatile("cp.async.cg.shared.global [%0], [%1], 16;"
                 :: "r"(dst), "l"(src) : "memory");
}
#define CP_COMMIT() asm volatile("cp.async.commit_group;" ::: "memory")
#define CP_WAIT0()  asm volatile("cp.async.wait_group 0;" ::: "memory")

__device__ __forceinline__ uint32_t prmt(uint32_t a, uint32_t b, uint32_t sel) {
    uint32_t d;
    asm("prmt.b32 %0, %1, %2, %3;" : "=r"(d) : "r"(a), "r"(b), "r"(sel));
    return d;
}
__device__ __forceinline__ void sts128(uint32_t a, uint32_t x, uint32_t y,
                                       uint32_t z, uint32_t w) {
    asm volatile("st.shared.v4.b32 [%0], {%1,%2,%3,%4};"
                 :: "r"(a), "r"(x), "r"(y), "r"(z), "r"(w) : "memory");
}
__device__ __forceinline__ void ldsm_x4(uint32_t* r, uint32_t addr) {
    asm volatile("ldmatrix.sync.aligned.m8n8.x4.shared.b16 {%0,%1,%2,%3}, [%4];"
                 : "=r"(r[0]), "=r"(r[1]), "=r"(r[2]), "=r"(r[3]) : "r"(addr));
}
__device__ __forceinline__ void ldsm_x4t(uint32_t* r, uint32_t addr) {
    asm volatile("ldmatrix.sync.aligned.m8n8.x4.trans.shared.b16 {%0,%1,%2,%3}, [%4];"
                 : "=r"(r[0]), "=r"(r[1]), "=r"(r[2]), "=r"(r[3]) : "r"(addr));
}
__device__ __forceinline__ void mma_bf16(float* c, const uint32_t* a, const uint32_t* b) {
    asm volatile(
        "mma.sync.aligned.m16n8k16.row.col.f32.bf16.bf16.f32 "
        "{%0,%1,%2,%3}, {%4,%5,%6,%7}, {%8,%9}, {%0,%1,%2,%3};"
        : "+f"(c[0]), "+f"(c[1]), "+f"(c[2]), "+f"(c[3])
        : "r"(a[0]), "r"(a[1]), "r"(a[2]), "r"(a[3]), "r"(b[0]), "r"(b[1]));
}

__device__ __forceinline__ void bf_split(float v, unsigned short& hu, unsigned short& lu) {
    __nv_bfloat16 h = __float2bfloat16(v);
    float hf = __bfloat162float(h);
    __nv_bfloat16 l = __float2bfloat16(v - hf);
    hu = reinterpret_cast<unsigned short&>(h);
    lu = reinterpret_cast<unsigned short&>(l);
}

// ======================= fused prep kernel ==================================
#define XPK_BLOCKS   ((NPIX + 255) / 256)
#define WOFF_ELEMS   (NSTG * 2 * 2 * 128 * 32)
#define WOFF_BLOCKS  ((WOFF_ELEMS + 255) / 256)
#define WPW_ELEMS    (NSTG_PW * 2 * 2 * 128 * 32)
#define WPW_BLOCKS   ((WPW_ELEMS + 255) / 256)

__global__ void prep_k(const float* __restrict__ x,
                       const float* __restrict__ ow,
                       const float* __restrict__ pw)
{
    const int blk = blockIdx.x;
    if (blk < XPK_BLOCKS) {
        int i = blk * 256 + threadIdx.x;
        if (i >= NPIX) return;
        unsigned short hu, lu;
        bf_split(x[i], hu, lu);
        g_xpk[GUARD + i] = (uint32_t)hu | ((uint32_t)lu << 16);
    } else if (blk < XPK_BLOCKS + WOFF_BLOCKS) {
        int idx = (blk - XPK_BLOCKS) * 256 + threadIdx.x;
        if (idx >= WOFF_ELEMS) return;
        int kk = idx & 31;
        int m  = (idx >> 5) & 127;
        int split = (idx >> 12) & 1;
        int mh = (idx >> 13) & 1;
        int t  = idx >> 14;
        int cin = (t & 3) * 32 + kk;
        int s   = t >> 2;
        int mg  = mh * 128 + m;
        float v = ow[mg * 1152 + cin * 9 + s];
        unsigned short hu, lu;
        bf_split(v, hu, lu);
        g_Aoffbf[idx] = split ? lu : hu;
    } else {
        int idx = (blk - XPK_BLOCKS - WOFF_BLOCKS) * 256 + threadIdx.x;
        if (idx >= WPW_ELEMS) return;
        int kk = idx & 31;
        int m  = (idx >> 5) & 127;
        int split = (idx >> 12) & 1;
        int mh = (idx >> 13) & 1;
        int t  = idx >> 14;
        int cin = t * 32 + kk;
        int mg  = mh * 128 + m;
        float v = pw[mg * 128 + cin];
        unsigned short hu, lu;
        bf_split(v, hu, lu);
        g_Apwbf[idx] = split ? lu : hu;
    }
}

// ======================= shared tile geometry ==============================
#define SA_BUF   20480
#define SA_SPL   10240
#define SB_BASE  40960
#define SB_BUF   17408
#define SB_SPL   8704
#define TILE_SMEM 75776

// ======================= offset conv: bf16-split mma (R15) =================
__global__ __launch_bounds__(256, 2)
void offconv_mma(const unsigned short* __restrict__ Abf,
                 const uint32_t* __restrict__ xpk,   // guard-adjusted base
                 const float* __restrict__ bias,
                 float* __restrict__ Odst)
{
    extern __shared__ char smem[];
    const uint32_t sA = smem_u32(smem);
    const uint32_t sB = sA + SB_BASE;

    const int tid  = threadIdx.x;
    const int lane = tid & 31;
    const int wid  = tid >> 5;
    const int mw   = wid & 1;
    const int nw   = wid >> 1;
    const int khrot = wid & 1;

    const int mhalf   = blockIdx.y;
    const int b       = blockIdx.x / 98;
    const int remBase = (blockIdx.x % 98) * 128;

    const int krow   = tid >> 3;
    const int pstart = (tid & 7) * 16;
    uint32_t mw0 = 0, mw1 = 0, mh0 = 0, mh1 = 0;
#pragma unroll
    for (int i = 0; i < 16; i++) {
        int rem = remBase + pstart + i;
        int h = rem / WW, w = rem - h * WW;
        if (w == 0)       mw0 |= 1u << i;
        if (w == WW - 1)  mw1 |= 1u << i;
        if (h == 0)       mh0 |= 1u << i;
        if (h == HH - 1)  mh1 |= 1u << i;
    }

    const int am     = tid & 127;
    const int asplit = tid >> 7;

    uint32_t v[16];

    auto cpA = [&](int t, int buf) {
        const unsigned short* src =
            Abf + (((size_t)(t * 2 + mhalf) * 2 + asplit) * 128 + am) * 32;
        uint32_t dst = sA + buf * SA_BUF + asplit * SA_SPL + am * 80;
        cp16(dst,      src);
        cp16(dst + 16, src + 8);
        cp16(dst + 32, src + 16);
        cp16(dst + 48, src + 24);
    };

    auto ldgB = [&](int t) {
        const int s   = t >> 2;
        const int dh  = s / 3 - 1;
        const int dw  = s % 3 - 1;
        const int cin = (t & 3) * 32 + krow;
        const uint32_t mask = ((dw < 0) ? mw0 : ((dw > 0) ? mw1 : 0u))
                            | ((dh < 0) ? mh0 : ((dh > 0) ? mh1 : 0u));
        const uint32_t* base = xpk + ((size_t)b * CC + cin) * HW
                             + remBase + pstart + dh * WW;
        uint4 q0 = *reinterpret_cast<const uint4*>(base);
        uint4 q1 = *reinterpret_cast<const uint4*>(base + 4);
        uint4 q2 = *reinterpret_cast<const uint4*>(base + 8);
        uint4 q3 = *reinterpret_cast<const uint4*>(base + 12);
        if (dw == 0) {
            v[0]=q0.x;  v[1]=q0.y;  v[2]=q0.z;  v[3]=q0.w;
            v[4]=q1.x;  v[5]=q1.y;  v[6]=q1.z;  v[7]=q1.w;
            v[8]=q2.x;  v[9]=q2.y;  v[10]=q2.z; v[11]=q2.w;
            v[12]=q3.x; v[13]=q3.y; v[14]=q3.z; v[15]=q3.w;
        } else if (dw > 0) {
            uint32_t e = __ldg(base + 16);
            v[0]=q0.y;  v[1]=q0.z;  v[2]=q0.w;  v[3]=q1.x;
            v[4]=q1.y;  v[5]=q1.z;  v[6]=q1.w;  v[7]=q2.x;
            v[8]=q2.y;  v[9]=q2.z;  v[10]=q2.w; v[11]=q3.x;
            v[12]=q3.y; v[13]=q3.z; v[14]=q3.w; v[15]=e;
        } else {
            uint32_t e = __ldg(base - 1);
            v[0]=e;     v[1]=q0.x;  v[2]=q0.y;  v[3]=q0.z;
            v[4]=q0.w;  v[5]=q1.x;  v[6]=q1.y;  v[7]=q1.z;
            v[8]=q1.w;  v[9]=q2.x;  v[10]=q2.y; v[11]=q2.z;
            v[12]=q2.w; v[13]=q3.x; v[14]=q3.y; v[15]=q3.z;
        }
        if (mask) {
#pragma unroll
            for (int i = 0; i < 16; i++)
                if ((mask >> i) & 1u) v[i] = 0u;
        }
    };

    auto stsB = [&](int buf) {
        uint32_t ph[8], pl[8];
#pragma unroll
        for (int j = 0; j < 8; j++) {
            ph[j] = prmt(v[2 * j], v[2 * j + 1], 0x5410);
            pl[j] = prmt(v[2 * j], v[2 * j + 1], 0x7632);
        }
        uint32_t d0 = sB + buf * SB_BUF + krow * 272 + pstart * 2;
        sts128(d0,               ph[0], ph[1], ph[2], ph[3]);
        sts128(d0 + 16,          ph[4], ph[5], ph[6], ph[7]);
        sts128(d0 + SB_SPL,      pl[0], pl[1], pl[2], pl[3]);
        sts128(d0 + SB_SPL + 16, pl[4], pl[5], pl[6], pl[7]);
    };

    float acc[4][4][4];
#pragma unroll
    for (int mt = 0; mt < 4; mt++)
#pragma unroll
        for (int nt = 0; nt < 4; nt++)
#pragma unroll
            for (int r = 0; r < 4; r++) acc[mt][nt][r] = 0.f;

    const uint32_t aOff = (uint32_t)((mw * 64 + (lane & 15)) * 80 + (lane >> 4) * 16);
    const uint32_t bOff = (uint32_t)((lane & 15) * 272 + nw * 64 + (lane >> 4) * 16);

    cpA(0, 0);
    CP_COMMIT();
    ldgB(0);
    stsB(0);

    for (int t = 0; t < NSTG; t++) {
        const int buf = t & 1;
        CP_WAIT0();
        __syncthreads();

        if (t + 1 < NSTG) ldgB(t + 1);

        const uint32_t aH = sA + buf * SA_BUF + aOff;
        const uint32_t aL = aH + SA_SPL;
        const uint32_t bH = sB + buf * SB_BUF + bOff;
        const uint32_t bL = bH + SB_SPL;
#pragma unroll
        for (int kh2 = 0; kh2 < 2; kh2++) {
            const int kh = kh2 ^ khrot;
            uint32_t bh[2][4], bl[2][4];
#pragma unroll
            for (int ntp = 0; ntp < 2; ntp++) {
                ldsm_x4t(bh[ntp], bH + kh * 4352 + ntp * 32);
                ldsm_x4t(bl[ntp], bL + kh * 4352 + ntp * 32);
            }
#pragma unroll
            for (int mt = 0; mt < 4; mt++) {
                uint32_t ah[4], al[4];
                ldsm_x4(ah, aH + mt * 1280 + kh * 32);
                ldsm_x4(al, aL + mt * 1280 + kh * 32);
#pragma unroll
                for (int nt = 0; nt < 4; nt++) {
                    const uint32_t* pbh = &bh[nt >> 1][2 * (nt & 1)];
                    const uint32_t* pbl = &bl[nt >> 1][2 * (nt & 1)];
                    mma_bf16(acc[mt][nt], ah, pbh);
                    mma_bf16(acc[mt][nt], ah, pbl);
                    mma_bf16(acc[mt][nt], al, pbh);
                }
            }
            if (kh2 == 0 && t + 1 < NSTG) {
                stsB(buf ^ 1);
                cpA(t + 1, buf ^ 1);
                CP_COMMIT();
            }
        }
    }

    const int ml = lane >> 2;
    const int nl = 2 * (lane & 3);
#pragma unroll
    for (int mt = 0; mt < 4; mt++) {
        const int mg0 = mhalf * 128 + mw * 64 + mt * 16 + ml;
        const float b0 = bias[mg0];
        const float b1 = bias[mg0 + 8];
        float* r0 = Odst + ((size_t)b * MOFF + mg0) * HW + remBase + nw * 32 + nl;
        float* r1 = r0 + (size_t)8 * HW;
#pragma unroll
        for (int nt = 0; nt < 4; nt++) {
            float2 o0, o1;
            o0.x = tanhf(acc[mt][nt][0] + b0);
            o0.y = tanhf(acc[mt][nt][1] + b0);
            o1.x = tanhf(acc[mt][nt][2] + b1);
            o1.y = tanhf(acc[mt][nt][3] + b1);
            *reinterpret_cast<float2*>(r0 + nt * 8) = o0;
            *reinterpret_cast<float2*>(r1 + nt * 8) = o1;
        }
    }
}

// ======================= pointwise conv: 2 pixel tiles per CTA =============
// 8 chained pipeline stages: g = tile*4 + kt; epilogue after each tile.
__global__ __launch_bounds__(256, 2)
void pwconv_mma(const unsigned short* __restrict__ Abf,
                const unsigned short* __restrict__ shi,
                const unsigned short* __restrict__ slo,
                float* __restrict__ Cdst)
{
    extern __shared__ char smem[];
    const uint32_t sA = smem_u32(smem);
    const uint32_t sB = sA + SB_BASE;

    const int tid  = threadIdx.x;
    const int lane = tid & 31;
    const int wid  = tid >> 5;
    const int mw   = wid & 1;
    const int nw   = wid >> 1;
    const int khrot = wid & 1;

    const int mhalf   = blockIdx.y;
    const int b       = blockIdx.x / 49;
    const int remBase = (blockIdx.x % 49) * 256;   // two 128-px tiles

    const int krow   = tid >> 3;
    const int pstart = (tid & 7) * 16;

    const int am     = tid & 127;
    const int asplit = tid >> 7;

    // g = tile*4 + kt
    auto load_stage = [&](int g, int buf) {
        const int kt   = g & 3;
        const int tile = g >> 2;
        {
            const unsigned short* src =
                Abf + (((size_t)(kt * 2 + mhalf) * 2 + asplit) * 128 + am) * 32;
            uint32_t dst = sA + buf * SA_BUF + asplit * SA_SPL + am * 80;
            cp16(dst,      src);
            cp16(dst + 16, src + 8);
            cp16(dst + 32, src + 16);
            cp16(dst + 48, src + 24);
        }
        {
            const int cin = kt * 32 + krow;
            const size_t so = ((size_t)b * CC + cin) * HW
                            + remBase + tile * 128 + pstart;
            uint32_t d0 = sB + buf * SB_BUF + krow * 272 + pstart * 2;
            cp16(d0,               shi + so);
            cp16(d0 + 16,          shi + so + 8);
            cp16(d0 + SB_SPL,      slo + so);
            cp16(d0 + SB_SPL + 16, slo + so + 8);
        }
    };

    float acc[4][4][4];
#pragma unroll
    for (int mt = 0; mt < 4; mt++)
#pragma unroll
        for (int nt = 0; nt < 4; nt++)
#pragma unroll
            for (int r = 0; r < 4; r++) acc[mt][nt][r] = 0.f;

    const uint32_t aOff = (uint32_t)((mw * 64 + (lane & 15)) * 80 + (lane >> 4) * 16);
    const uint32_t bOff = (uint32_t)((lane & 15) * 272 + nw * 64 + (lane >> 4) * 16);

    const int ml = lane >> 2;
    const int nl = 2 * (lane & 3);

    load_stage(0, 0);
    CP_COMMIT();

    constexpr int NG = 2 * NSTG_PW;   // 8
    for (int g = 0; g < NG; g++) {
        const int buf = g & 1;
        if (g + 1 < NG) {
            load_stage(g + 1, buf ^ 1);
            CP_COMMIT();
            asm volatile("cp.async.wait_group 1;" ::: "memory");
        } else {
            CP_WAIT0();
        }
        __syncthreads();

        const uint32_t aH = sA + buf * SA_BUF + aOff;
        const uint32_t aL = aH + SA_SPL;
        const uint32_t bH = sB + buf * SB_BUF + bOff;
        const uint32_t bL = bH + SB_SPL;
#pragma unroll
        for (int kh2 = 0; kh2 < 2; kh2++) {
            const int kh = kh2 ^ khrot;
            uint32_t bh[2][4], bl[2][4];
#pragma unroll
            for (int ntp = 0; ntp < 2; ntp++) {
                ldsm_x4t(bh[ntp], bH + kh * 4352 + ntp * 32);
                ldsm_x4t(bl[ntp], bL + kh * 4352 + ntp * 32);
            }
#pragma unroll
            for (int mt = 0; mt < 4; mt++) {
                uint32_t ah[4], al[4];
                ldsm_x4(ah, aH + mt * 1280 + kh * 32);
                ldsm_x4(al, aL + mt * 1280 + kh * 32);
#pragma unroll
                for (int nt = 0; nt < 4; nt++) {
                    const uint32_t* pbh = &bh[nt >> 1][2 * (nt & 1)];
                    const uint32_t* pbl = &bl[nt >> 1][2 * (nt & 1)];
                    mma_bf16(acc[mt][nt], ah, pbh);
                    mma_bf16(acc[mt][nt], ah, pbl);
                    mma_bf16(acc[mt][nt], al, pbh);
                }
            }
        }
        __syncthreads();

        // tile boundary: epilogue + reset acc
        if ((g & 3) == 3) {
            const int tile = g >> 2;
            const int remB = remBase + tile * 128;
#pragma unroll
            for (int mt = 0; mt < 4; mt++) {
                const int mg0 = mhalf * 128 + mw * 64 + mt * 16 + ml;
                float* r0 = Cdst + ((size_t)b * 256 + mg0) * HW + remB + nw * 32 + nl;
                float* r1 = r0 + (size_t)8 * HW;
#pragma unroll
                for (int nt = 0; nt < 4; nt++) {
                    float2 o0, o1;
                    o0.x = acc[mt][nt][0];
                    o0.y = acc[mt][nt][1];
                    o1.x = acc[mt][nt][2];
                    o1.y = acc[mt][nt][3];
                    *reinterpret_cast<float2*>(r0 + nt * 8) = o0;
                    *reinterpret_cast<float2*>(r1 + nt * 8) = o1;
                    acc[mt][nt][0] = 0.f;
                    acc[mt][nt][1] = 0.f;
                    acc[mt][nt][2] = 0.f;
                    acc[mt][nt][3] = 0.f;
                }
            }
        }
    }
}

// ======================= fused depthwise + grid sample =====================
#define DWGS_SMEM (HW * 4)

__global__ __launch_bounds__(1024)
void dwgs_k(const float* __restrict__ x,
            const float* __restrict__ wgt,
            const float* __restrict__ off,
            unsigned short* __restrict__ dhi,
            unsigned short* __restrict__ dlo)
{
    extern __shared__ float img[];
    const int bc  = blockIdx.x;
    const int b   = bc / CC;
    const int c   = bc % CC;
    const int tid = threadIdx.x;

    float wreg[9];
#pragma unroll
    for (int i = 0; i < 9; i++) wreg[i] = __ldg(wgt + c * 9 + i);

    const float* xp = x + (size_t)bc * HW;
    for (int it = 0; it < 4; it++) {
        const int p = (tid + 1024 * it) * 4;
        if (p >= HW) break;
        const int h = p / WW;
        const int w = p - h * WW;
        float a0 = 0.f, a1 = 0.f, a2 = 0.f, a3 = 0.f;
#pragma unroll
        for (int kh = 0; kh < 3; kh++) {
            const int ih = h + kh - 1;
            if ((unsigned)ih >= (unsigned)HH) continue;
            const float* xr = xp + ih * WW + w;
            const float4 q = *reinterpret_cast<const float4*>(xr);
            const float left  = (w > 0)        ? __ldg(xr - 1) : 0.f;
            const float right = (w + 4 < WW)   ? __ldg(xr + 4) : 0.f;
            const float w0 = wreg[kh * 3 + 0];
            const float w1 = wreg[kh * 3 + 1];
            const float w2 = wreg[kh * 3 + 2];
            a0 = fmaf(left, w0, a0); a0 = fmaf(q.x, w1, a0); a0 = fmaf(q.y, w2, a0);
            a1 = fmaf(q.x,  w0, a1); a1 = fmaf(q.y, w1, a1); a1 = fmaf(q.z, w2, a1);
            a2 = fmaf(q.y,  w0, a2); a2 = fmaf(q.z, w1, a2); a2 = fmaf(q.w, w2, a2);
            a3 = fmaf(q.z,  w0, a3); a3 = fmaf(q.w, w1, a3); a3 = fmaf(right, w2, a3);
        }
        *reinterpret_cast<float4*>(img + p) = make_float4(a0, a1, a2, a3);
    }
    __syncthreads();

    const bool bx_is_gx = (2 * c) < CC;
    const bool by_is_gx = (2 * c + 1) < CC;

    const float* offx_p = off + ((size_t)b * MOFF + 2 * c) * HW;
    const float* offy_p = offx_p + HW;
    unsigned short* oh = dhi + (size_t)bc * HW;
    unsigned short* ol = dlo + (size_t)bc * HW;

    for (int it = 0; it < 4; it++) {
        const int p = (tid + 1024 * it) * 4;
        if (p >= HW) break;
        const int h = p / WW;
        const int w = p - h * WW;

        const float4 ox4 = *reinterpret_cast<const float4*>(offx_p + p);
        const float4 oy4 = *reinterpret_cast<const float4*>(offy_p + p);
        const float offx_a[4] = {ox4.x, ox4.y, ox4.z, ox4.w};
        const float offy_a[4] = {oy4.x, oy4.y, oy4.z, oy4.w};

        const float gy = -1.f + 2.f * (float)h / (float)(HH - 1);
        unsigned short hs[4], ls[4];
#pragma unroll
        for (int j = 0; j < 4; j++) {
            const float gx = -1.f + 2.f * (float)(w + j) / (float)(WW - 1);
            const float basex = bx_is_gx ? gx : gy;
            const float basey = by_is_gx ? gx : gy;

            float sx = fminf(fmaxf(basex + offx_a[j], -1.f), 1.f);
            float sy = fminf(fmaxf(basey + offy_a[j], -1.f), 1.f);

            const float ix = (sx + 1.f) * ((float)WW * 0.5f) - 0.5f;
            const float iy = (sy + 1.f) * ((float)HH * 0.5f) - 0.5f;

            const float x0f = floorf(ix);
            const float y0f = floorf(iy);
            const float wx  = ix - x0f;
            const float wy  = iy - y0f;
            const int x0 = (int)x0f;
            const int y0 = (int)y0f;

            auto gather = [&](int yi, int xi) -> float {
                if ((unsigned)yi < (unsigned)HH && (unsigned)xi < (unsigned)WW)
                    return img[yi * WW + xi];
                return 0.f;
            };

            const float v00 = gather(y0,     x0);
            const float v01 = gather(y0,     x0 + 1);
            const float v10 = gather(y0 + 1, x0);
            const float v11 = gather(y0 + 1, x0 + 1);

            const float r = v00 * (1.f - wx) * (1.f - wy)
                          + v01 * wx         * (1.f - wy)
                          + v10 * (1.f - wx) * wy
                          + v11 * wx         * wy;

            bf_split(r, hs[j], ls[j]);
        }
        *reinterpret_cast<ushort4*>(oh + p) = make_ushort4(hs[0], hs[1], hs[2], hs[3]);
        *reinterpret_cast<ushort4*>(ol + p) = make_ushort4(ls[0], ls[1], ls[2], ls[3]);
    }
}

// ======================= launch ============================================
extern "C" void kernel_launch(void* const* d_in, const int* in_sizes, int n_in,
                              void* d_out, int out_size)
{
    const float* x        = (const float*)d_in[0];
    const float* depth_w  = (const float*)d_in[1];
    const float* point_w  = (const float*)d_in[2];
    const float* offset_w = (const float*)d_in[3];
    const float* offset_b = (const float*)d_in[4];
    float* out = (float*)d_out;

    float* offset_p; cudaGetSymbolAddress((void**)&offset_p, g_offset);
    uint32_t* xpk_p; cudaGetSymbolAddress((void**)&xpk_p,    g_xpk);
    unsigned short* shi_p; cudaGetSymbolAddress((void**)&shi_p, g_shi);
    unsigned short* slo_p; cudaGetSymbolAddress((void**)&slo_p, g_slo);
    unsigned short* aoff_p; cudaGetSymbolAddress((void**)&aoff_p, g_Aoffbf);
    unsigned short* apw_p;  cudaGetSymbolAddress((void**)&apw_p,  g_Apwbf);

    cudaFuncSetAttribute(offconv_mma,
                         cudaFuncAttributeMaxDynamicSharedMemorySize, TILE_SMEM);
    cudaFuncSetAttribute(pwconv_mma,
                         cudaFuncAttributeMaxDynamicSharedMemorySize, TILE_SMEM);
    cudaFuncSetAttribute(dwgs_k,
                         cudaFuncAttributeMaxDynamicSharedMemorySize, DWGS_SMEM);

    // 0) fused prep
    prep_k<<<XPK_BLOCKS + WOFF_BLOCKS + WPW_BLOCKS, 256>>>(x, offset_w, point_w);

    // 1) offset conv + bias + tanh
    {
        dim3 g(98 * BB, 2);
        offconv_mma<<<g, 256, TILE_SMEM>>>(aoff_p, xpk_p + GUARD, offset_b, offset_p);
    }

    // 2+3) fused depthwise + grid sample -> split planes
    dwgs_k<<<BB * CC, 1024, DWGS_SMEM>>>(x, depth_w, offset_p, shi_p, slo_p);

    // 4) pointwise 1x1 (bf16-split mma, 2 tiles per CTA) -> out
    {
        dim3 g(49 * BB, 2);
        pwconv_mma<<<g, 256, TILE_SMEM>>>(apw_p, shi_p, slo_p, out);
    }
}

// round 17
// speedup vs baseline: 1.0118x; 1.0118x over previous
#include <cuda_runtime.h>
#include <cuda_bf16.h>
#include <cstdint>
#include <math.h>

// ---------------------------------------------------------------------------
// CDConv: offset-conv(3x3,128->256, bf16-split mma.sync)+tanh ->
//         fused depthwise+grid_sample(->bf16 hi/lo planes) ->
//         pointwise(1x1, bf16-split mma)
// B=16, C=128, H=W=112, OUTC=256
// R17 = R15 (best structure) + dwgs@1024 + pwconv streaming output stores.
// ---------------------------------------------------------------------------

#define BB   16
#define CC   128
#define HH   112
#define WW   112
#define HW   12544
#define MOFF 256
#define NSTG 36               // offset conv: K=1152 / 32
#define NSTG_PW 4             // pointwise:  K=128 / 32

#define NPIX  (BB * CC * HW)
#define GUARD 128

__device__ float    g_offset[BB * MOFF * HW];
__device__ uint32_t g_xpk[NPIX + 2 * GUARD];                 // {bf16 hi | lo<<16}
__device__ unsigned short g_shi[NPIX];                       // sampled hi plane
__device__ unsigned short g_slo[NPIX];                       // sampled lo plane
__device__ unsigned short g_Aoffbf[NSTG * 2 * 2 * 128 * 32]; // [t][mh][split][m][k]
__device__ unsigned short g_Apwbf[NSTG_PW * 2 * 2 * 128 * 32];

// ======================= helpers ==========================================
__device__ __forceinline__ uint32_t smem_u32(const void* p) {
    uint32_t a;
    asm("{ .reg .u64 t; cvta.to.shared.u64 t, %1; cvt.u32.u64 %0, t; }"
        : "=r"(a) : "l"(p));
    return a;
}
__device__ __forceinline__ void cp16(uint32_t dst, const void* src) {
    asm volatile("cp.async.cg.shared.global [%0], [%1], 16;"
                 :: "r"(dst), "l"(src) : "memory");
}
#define CP_COMMIT() asm volatile("cp.async.commit_group;" ::: "memory")
#define CP_WAIT0()  asm volatile("cp.async.wait_group 0;" ::: "memory")

__device__ __forceinline__ uint32_t prmt(uint32_t a, uint32_t b, uint32_t sel) {
    uint32_t d;
    asm("prmt.b32 %0, %1, %2, %3;" : "=r"(d) : "r"(a), "r"(b), "r"(sel));
    return d;
}
__device__ __forceinline__ void sts128(uint32_t a, uint32_t x, uint32_t y,
                                       uint32_t z, uint32_t w) {
    asm volatile("st.shared.v4.b32 [%0], {%1,%2,%3,%4};"
                 :: "r"(a), "r"(x), "r"(y), "r"(z), "r"(w) : "memory");
}
__device__ __forceinline__ void stg_cs_f2(float* p, float x, float y) {
    asm volatile("st.global.cs.v2.f32 [%0], {%1,%2};"
                 :: "l"(p), "f"(x), "f"(y) : "memory");
}
__device__ __forceinline__ void ldsm_x4(uint32_t* r, uint32_t addr) {
    asm volatile("ldmatrix.sync.aligned.m8n8.x4.shared.b16 {%0,%1,%2,%3}, [%4];"
                 : "=r"(r[0]), "=r"(r[1]), "=r"(r[2]), "=r"(r[3]) : "r"(addr));
}
__device__ __forceinline__ void ldsm_x4t(uint32_t* r, uint32_t addr) {
    asm volatile("ldmatrix.sync.aligned.m8n8.x4.trans.shared.b16 {%0,%1,%2,%3}, [%4];"
                 : "=r"(r[0]), "=r"(r[1]), "=r"(r[2]), "=r"(r[3]) : "r"(addr));
}
__device__ __forceinline__ void mma_bf16(float* c, const uint32_t* a, const uint32_t* b) {
    asm volatile(
        "mma.sync.aligned.m16n8k16.row.col.f32.bf16.bf16.f32 "
        "{%0,%1,%2,%3}, {%4,%5,%6,%7}, {%8,%9}, {%0,%1,%2,%3};"
        : "+f"(c[0]), "+f"(c[1]), "+f"(c[2]), "+f"(c[3])
        : "r"(a[0]), "r"(a[1]), "r"(a[2]), "r"(a[3]), "r"(b[0]), "r"(b[1]));
}

__device__ __forceinline__ void bf_split(float v, unsigned short& hu, unsigned short& lu) {
    __nv_bfloat16 h = __float2bfloat16(v);
    float hf = __bfloat162float(h);
    __nv_bfloat16 l = __float2bfloat16(v - hf);
    hu = reinterpret_cast<unsigned short&>(h);
    lu = reinterpret_cast<unsigned short&>(l);
}

// ======================= fused prep kernel ==================================
#define XPK_BLOCKS   ((NPIX + 255) / 256)
#define WOFF_ELEMS   (NSTG * 2 * 2 * 128 * 32)
#define WOFF_BLOCKS  ((WOFF_ELEMS + 255) / 256)
#define WPW_ELEMS    (NSTG_PW * 2 * 2 * 128 * 32)
#define WPW_BLOCKS   ((WPW_ELEMS + 255) / 256)

__global__ void prep_k(const float* __restrict__ x,
                       const float* __restrict__ ow,
                       const float* __restrict__ pw)
{
    const int blk = blockIdx.x;
    if (blk < XPK_BLOCKS) {
        int i = blk * 256 + threadIdx.x;
        if (i >= NPIX) return;
        unsigned short hu, lu;
        bf_split(x[i], hu, lu);
        g_xpk[GUARD + i] = (uint32_t)hu | ((uint32_t)lu << 16);
    } else if (blk < XPK_BLOCKS + WOFF_BLOCKS) {
        int idx = (blk - XPK_BLOCKS) * 256 + threadIdx.x;
        if (idx >= WOFF_ELEMS) return;
        int kk = idx & 31;
        int m  = (idx >> 5) & 127;
        int split = (idx >> 12) & 1;
        int mh = (idx >> 13) & 1;
        int t  = idx >> 14;
        int cin = (t & 3) * 32 + kk;
        int s   = t >> 2;
        int mg  = mh * 128 + m;
        float v = ow[mg * 1152 + cin * 9 + s];
        unsigned short hu, lu;
        bf_split(v, hu, lu);
        g_Aoffbf[idx] = split ? lu : hu;
    } else {
        int idx = (blk - XPK_BLOCKS - WOFF_BLOCKS) * 256 + threadIdx.x;
        if (idx >= WPW_ELEMS) return;
        int kk = idx & 31;
        int m  = (idx >> 5) & 127;
        int split = (idx >> 12) & 1;
        int mh = (idx >> 13) & 1;
        int t  = idx >> 14;
        int cin = t * 32 + kk;
        int mg  = mh * 128 + m;
        float v = pw[mg * 128 + cin];
        unsigned short hu, lu;
        bf_split(v, hu, lu);
        g_Apwbf[idx] = split ? lu : hu;
    }
}

// ======================= shared tile geometry ==============================
#define SA_BUF   20480
#define SA_SPL   10240
#define SB_BASE  40960
#define SB_BUF   17408
#define SB_SPL   8704
#define TILE_SMEM 75776

// ======================= offset conv: bf16-split mma (R15) =================
__global__ __launch_bounds__(256, 2)
void offconv_mma(const unsigned short* __restrict__ Abf,
                 const uint32_t* __restrict__ xpk,   // guard-adjusted base
                 const float* __restrict__ bias,
                 float* __restrict__ Odst)
{
    extern __shared__ char smem[];
    const uint32_t sA = smem_u32(smem);
    const uint32_t sB = sA + SB_BASE;

    const int tid  = threadIdx.x;
    const int lane = tid & 31;
    const int wid  = tid >> 5;
    const int mw   = wid & 1;
    const int nw   = wid >> 1;
    const int khrot = wid & 1;

    const int mhalf   = blockIdx.y;
    const int b       = blockIdx.x / 98;
    const int remBase = (blockIdx.x % 98) * 128;

    const int krow   = tid >> 3;
    const int pstart = (tid & 7) * 16;
    uint32_t mw0 = 0, mw1 = 0, mh0 = 0, mh1 = 0;
#pragma unroll
    for (int i = 0; i < 16; i++) {
        int rem = remBase + pstart + i;
        int h = rem / WW, w = rem - h * WW;
        if (w == 0)       mw0 |= 1u << i;
        if (w == WW - 1)  mw1 |= 1u << i;
        if (h == 0)       mh0 |= 1u << i;
        if (h == HH - 1)  mh1 |= 1u << i;
    }

    const int am     = tid & 127;
    const int asplit = tid >> 7;

    uint32_t v[16];

    auto cpA = [&](int t, int buf) {
        const unsigned short* src =
            Abf + (((size_t)(t * 2 + mhalf) * 2 + asplit) * 128 + am) * 32;
        uint32_t dst = sA + buf * SA_BUF + asplit * SA_SPL + am * 80;
        cp16(dst,      src);
        cp16(dst + 16, src + 8);
        cp16(dst + 32, src + 16);
        cp16(dst + 48, src + 24);
    };

    auto ldgB = [&](int t) {
        const int s   = t >> 2;
        const int dh  = s / 3 - 1;
        const int dw  = s % 3 - 1;
        const int cin = (t & 3) * 32 + krow;
        const uint32_t mask = ((dw < 0) ? mw0 : ((dw > 0) ? mw1 : 0u))
                            | ((dh < 0) ? mh0 : ((dh > 0) ? mh1 : 0u));
        const uint32_t* base = xpk + ((size_t)b * CC + cin) * HW
                             + remBase + pstart + dh * WW;
        uint4 q0 = *reinterpret_cast<const uint4*>(base);
        uint4 q1 = *reinterpret_cast<const uint4*>(base + 4);
        uint4 q2 = *reinterpret_cast<const uint4*>(base + 8);
        uint4 q3 = *reinterpret_cast<const uint4*>(base + 12);
        if (dw == 0) {
            v[0]=q0.x;  v[1]=q0.y;  v[2]=q0.z;  v[3]=q0.w;
            v[4]=q1.x;  v[5]=q1.y;  v[6]=q1.z;  v[7]=q1.w;
            v[8]=q2.x;  v[9]=q2.y;  v[10]=q2.z; v[11]=q2.w;
            v[12]=q3.x; v[13]=q3.y; v[14]=q3.z; v[15]=q3.w;
        } else if (dw > 0) {
            uint32_t e = __ldg(base + 16);
            v[0]=q0.y;  v[1]=q0.z;  v[2]=q0.w;  v[3]=q1.x;
            v[4]=q1.y;  v[5]=q1.z;  v[6]=q1.w;  v[7]=q2.x;
            v[8]=q2.y;  v[9]=q2.z;  v[10]=q2.w; v[11]=q3.x;
            v[12]=q3.y; v[13]=q3.z; v[14]=q3.w; v[15]=e;
        } else {
            uint32_t e = __ldg(base - 1);
            v[0]=e;     v[1]=q0.x;  v[2]=q0.y;  v[3]=q0.z;
            v[4]=q0.w;  v[5]=q1.x;  v[6]=q1.y;  v[7]=q1.z;
            v[8]=q1.w;  v[9]=q2.x;  v[10]=q2.y; v[11]=q2.z;
            v[12]=q2.w; v[13]=q3.x; v[14]=q3.y; v[15]=q3.z;
        }
        if (mask) {
#pragma unroll
            for (int i = 0; i < 16; i++)
                if ((mask >> i) & 1u) v[i] = 0u;
        }
    };

    auto stsB = [&](int buf) {
        uint32_t ph[8], pl[8];
#pragma unroll
        for (int j = 0; j < 8; j++) {
            ph[j] = prmt(v[2 * j], v[2 * j + 1], 0x5410);
            pl[j] = prmt(v[2 * j], v[2 * j + 1], 0x7632);
        }
        uint32_t d0 = sB + buf * SB_BUF + krow * 272 + pstart * 2;
        sts128(d0,               ph[0], ph[1], ph[2], ph[3]);
        sts128(d0 + 16,          ph[4], ph[5], ph[6], ph[7]);
        sts128(d0 + SB_SPL,      pl[0], pl[1], pl[2], pl[3]);
        sts128(d0 + SB_SPL + 16, pl[4], pl[5], pl[6], pl[7]);
    };

    float acc[4][4][4];
#pragma unroll
    for (int mt = 0; mt < 4; mt++)
#pragma unroll
        for (int nt = 0; nt < 4; nt++)
#pragma unroll
            for (int r = 0; r < 4; r++) acc[mt][nt][r] = 0.f;

    const uint32_t aOff = (uint32_t)((mw * 64 + (lane & 15)) * 80 + (lane >> 4) * 16);
    const uint32_t bOff = (uint32_t)((lane & 15) * 272 + nw * 64 + (lane >> 4) * 16);

    cpA(0, 0);
    CP_COMMIT();
    ldgB(0);
    stsB(0);

    for (int t = 0; t < NSTG; t++) {
        const int buf = t & 1;
        CP_WAIT0();
        __syncthreads();

        if (t + 1 < NSTG) ldgB(t + 1);

        const uint32_t aH = sA + buf * SA_BUF + aOff;
        const uint32_t aL = aH + SA_SPL;
        const uint32_t bH = sB + buf * SB_BUF + bOff;
        const uint32_t bL = bH + SB_SPL;
#pragma unroll
        for (int kh2 = 0; kh2 < 2; kh2++) {
            const int kh = kh2 ^ khrot;
            uint32_t bh[2][4], bl[2][4];
#pragma unroll
            for (int ntp = 0; ntp < 2; ntp++) {
                ldsm_x4t(bh[ntp], bH + kh * 4352 + ntp * 32);
                ldsm_x4t(bl[ntp], bL + kh * 4352 + ntp * 32);
            }
#pragma unroll
            for (int mt = 0; mt < 4; mt++) {
                uint32_t ah[4], al[4];
                ldsm_x4(ah, aH + mt * 1280 + kh * 32);
                ldsm_x4(al, aL + mt * 1280 + kh * 32);
#pragma unroll
                for (int nt = 0; nt < 4; nt++) {
                    const uint32_t* pbh = &bh[nt >> 1][2 * (nt & 1)];
                    const uint32_t* pbl = &bl[nt >> 1][2 * (nt & 1)];
                    mma_bf16(acc[mt][nt], ah, pbh);
                    mma_bf16(acc[mt][nt], ah, pbl);
                    mma_bf16(acc[mt][nt], al, pbh);
                }
            }
            if (kh2 == 0 && t + 1 < NSTG) {
                stsB(buf ^ 1);
                cpA(t + 1, buf ^ 1);
                CP_COMMIT();
            }
        }
    }

    const int ml = lane >> 2;
    const int nl = 2 * (lane & 3);
#pragma unroll
    for (int mt = 0; mt < 4; mt++) {
        const int mg0 = mhalf * 128 + mw * 64 + mt * 16 + ml;
        const float b0 = bias[mg0];
        const float b1 = bias[mg0 + 8];
        float* r0 = Odst + ((size_t)b * MOFF + mg0) * HW + remBase + nw * 32 + nl;
        float* r1 = r0 + (size_t)8 * HW;
#pragma unroll
        for (int nt = 0; nt < 4; nt++) {
            float2 o0, o1;
            o0.x = tanhf(acc[mt][nt][0] + b0);
            o0.y = tanhf(acc[mt][nt][1] + b0);
            o1.x = tanhf(acc[mt][nt][2] + b1);
            o1.y = tanhf(acc[mt][nt][3] + b1);
            *reinterpret_cast<float2*>(r0 + nt * 8) = o0;
            *reinterpret_cast<float2*>(r1 + nt * 8) = o1;
        }
    }
}

// ======================= pointwise conv: bf16-split mma (R15) ==============
__global__ __launch_bounds__(256, 2)
void pwconv_mma(const unsigned short* __restrict__ Abf,
                const unsigned short* __restrict__ shi,
                const unsigned short* __restrict__ slo,
                float* __restrict__ Cdst)
{
    extern __shared__ char smem[];
    const uint32_t sA = smem_u32(smem);
    const uint32_t sB = sA + SB_BASE;

    const int tid  = threadIdx.x;
    const int lane = tid & 31;
    const int wid  = tid >> 5;
    const int mw   = wid & 1;
    const int nw   = wid >> 1;
    const int khrot = wid & 1;

    const int mhalf   = blockIdx.y;
    const int b       = blockIdx.x / 98;
    const int remBase = (blockIdx.x % 98) * 128;

    const int krow   = tid >> 3;
    const int pstart = (tid & 7) * 16;

    const int am     = tid & 127;
    const int asplit = tid >> 7;

    auto load_stage = [&](int t, int buf) {
        {
            const unsigned short* src =
                Abf + (((size_t)(t * 2 + mhalf) * 2 + asplit) * 128 + am) * 32;
            uint32_t dst = sA + buf * SA_BUF + asplit * SA_SPL + am * 80;
            cp16(dst,      src);
            cp16(dst + 16, src + 8);
            cp16(dst + 32, src + 16);
            cp16(dst + 48, src + 24);
        }
        {
            const int cin = t * 32 + krow;
            const size_t so = ((size_t)b * CC + cin) * HW + remBase + pstart;
            uint32_t d0 = sB + buf * SB_BUF + krow * 272 + pstart * 2;
            cp16(d0,               shi + so);
            cp16(d0 + 16,          shi + so + 8);
            cp16(d0 + SB_SPL,      slo + so);
            cp16(d0 + SB_SPL + 16, slo + so + 8);
        }
    };

    float acc[4][4][4];
#pragma unroll
    for (int mt = 0; mt < 4; mt++)
#pragma unroll
        for (int nt = 0; nt < 4; nt++)
#pragma unroll
            for (int r = 0; r < 4; r++) acc[mt][nt][r] = 0.f;

    const uint32_t aOff = (uint32_t)((mw * 64 + (lane & 15)) * 80 + (lane >> 4) * 16);
    const uint32_t bOff = (uint32_t)((lane & 15) * 272 + nw * 64 + (lane >> 4) * 16);

    load_stage(0, 0);
    CP_COMMIT();

    for (int t = 0; t < NSTG_PW; t++) {
        const int buf = t & 1;
        if (t + 1 < NSTG_PW) {
            load_stage(t + 1, buf ^ 1);
            CP_COMMIT();
            asm volatile("cp.async.wait_group 1;" ::: "memory");
        } else {
            CP_WAIT0();
        }
        __syncthreads();

        const uint32_t aH = sA + buf * SA_BUF + aOff;
        const uint32_t aL = aH + SA_SPL;
        const uint32_t bH = sB + buf * SB_BUF + bOff;
        const uint32_t bL = bH + SB_SPL;
#pragma unroll
        for (int kh2 = 0; kh2 < 2; kh2++) {
            const int kh = kh2 ^ khrot;
            uint32_t bh[2][4], bl[2][4];
#pragma unroll
            for (int ntp = 0; ntp < 2; ntp++) {
                ldsm_x4t(bh[ntp], bH + kh * 4352 + ntp * 32);
                ldsm_x4t(bl[ntp], bL + kh * 4352 + ntp * 32);
            }
#pragma unroll
            for (int mt = 0; mt < 4; mt++) {
                uint32_t ah[4], al[4];
                ldsm_x4(ah, aH + mt * 1280 + kh * 32);
                ldsm_x4(al, aL + mt * 1280 + kh * 32);
#pragma unroll
                for (int nt = 0; nt < 4; nt++) {
                    const uint32_t* pbh = &bh[nt >> 1][2 * (nt & 1)];
                    const uint32_t* pbl = &bl[nt >> 1][2 * (nt & 1)];
                    mma_bf16(acc[mt][nt], ah, pbh);
                    mma_bf16(acc[mt][nt], ah, pbl);
                    mma_bf16(acc[mt][nt], al, pbh);
                }
            }
        }
        __syncthreads();
    }

    const int ml = lane >> 2;
    const int nl = 2 * (lane & 3);
#pragma unroll
    for (int mt = 0; mt < 4; mt++) {
        const int mg0 = mhalf * 128 + mw * 64 + mt * 16 + ml;
        float* r0 = Cdst + ((size_t)b * 256 + mg0) * HW + remBase + nw * 32 + nl;
        float* r1 = r0 + (size_t)8 * HW;
#pragma unroll
        for (int nt = 0; nt < 4; nt++) {
            stg_cs_f2(r0 + nt * 8, acc[mt][nt][0], acc[mt][nt][1]);
            stg_cs_f2(r1 + nt * 8, acc[mt][nt][2], acc[mt][nt][3]);
        }
    }
}

// ======================= fused depthwise + grid sample =====================
#define DWGS_SMEM (HW * 4)

__global__ __launch_bounds__(1024)
void dwgs_k(const float* __restrict__ x,
            const float* __restrict__ wgt,
            const float* __restrict__ off,
            unsigned short* __restrict__ dhi,
            unsigned short* __restrict__ dlo)
{
    extern __shared__ float img[];
    const int bc  = blockIdx.x;
    const int b   = bc / CC;
    const int c   = bc % CC;
    const int tid = threadIdx.x;

    float wreg[9];
#pragma unroll
    for (int i = 0; i < 9; i++) wreg[i] = __ldg(wgt + c * 9 + i);

    const float* xp = x + (size_t)bc * HW;
    for (int it = 0; it < 4; it++) {
        const int p = (tid + 1024 * it) * 4;
        if (p >= HW) break;
        const int h = p / WW;
        const int w = p - h * WW;
        float a0 = 0.f, a1 = 0.f, a2 = 0.f, a3 = 0.f;
#pragma unroll
        for (int kh = 0; kh < 3; kh++) {
            const int ih = h + kh - 1;
            if ((unsigned)ih >= (unsigned)HH) continue;
            const float* xr = xp + ih * WW + w;
            const float4 q = *reinterpret_cast<const float4*>(xr);
            const float left  = (w > 0)        ? __ldg(xr - 1) : 0.f;
            const float right = (w + 4 < WW)   ? __ldg(xr + 4) : 0.f;
            const float w0 = wreg[kh * 3 + 0];
            const float w1 = wreg[kh * 3 + 1];
            const float w2 = wreg[kh * 3 + 2];
            a0 = fmaf(left, w0, a0); a0 = fmaf(q.x, w1, a0); a0 = fmaf(q.y, w2, a0);
            a1 = fmaf(q.x,  w0, a1); a1 = fmaf(q.y, w1, a1); a1 = fmaf(q.z, w2, a1);
            a2 = fmaf(q.y,  w0, a2); a2 = fmaf(q.z, w1, a2); a2 = fmaf(q.w, w2, a2);
            a3 = fmaf(q.z,  w0, a3); a3 = fmaf(q.w, w1, a3); a3 = fmaf(right, w2, a3);
        }
        *reinterpret_cast<float4*>(img + p) = make_float4(a0, a1, a2, a3);
    }
    __syncthreads();

    const bool bx_is_gx = (2 * c) < CC;
    const bool by_is_gx = (2 * c + 1) < CC;

    const float* offx_p = off + ((size_t)b * MOFF + 2 * c) * HW;
    const float* offy_p = offx_p + HW;
    unsigned short* oh = dhi + (size_t)bc * HW;
    unsigned short* ol = dlo + (size_t)bc * HW;

    for (int it = 0; it < 4; it++) {
        const int p = (tid + 1024 * it) * 4;
        if (p >= HW) break;
        const int h = p / WW;
        const int w = p - h * WW;

        const float4 ox4 = *reinterpret_cast<const float4*>(offx_p + p);
        const float4 oy4 = *reinterpret_cast<const float4*>(offy_p + p);
        const float offx_a[4] = {ox4.x, ox4.y, ox4.z, ox4.w};
        const float offy_a[4] = {oy4.x, oy4.y, oy4.z, oy4.w};

        const float gy = -1.f + 2.f * (float)h / (float)(HH - 1);
        unsigned short hs[4], ls[4];
#pragma unroll
        for (int j = 0; j < 4; j++) {
            const float gx = -1.f + 2.f * (float)(w + j) / (float)(WW - 1);
            const float basex = bx_is_gx ? gx : gy;
            const float basey = by_is_gx ? gx : gy;

            float sx = fminf(fmaxf(basex + offx_a[j], -1.f), 1.f);
            float sy = fminf(fmaxf(basey + offy_a[j], -1.f), 1.f);

            const float ix = (sx + 1.f) * ((float)WW * 0.5f) - 0.5f;
            const float iy = (sy + 1.f) * ((float)HH * 0.5f) - 0.5f;

            const float x0f = floorf(ix);
            const float y0f = floorf(iy);
            const float wx  = ix - x0f;
            const float wy  = iy - y0f;
            const int x0 = (int)x0f;
            const int y0 = (int)y0f;

            auto gather = [&](int yi, int xi) -> float {
                if ((unsigned)yi < (unsigned)HH && (unsigned)xi < (unsigned)WW)
                    return img[yi * WW + xi];
                return 0.f;
            };

            const float v00 = gather(y0,     x0);
            const float v01 = gather(y0,     x0 + 1);
            const float v10 = gather(y0 + 1, x0);
            const float v11 = gather(y0 + 1, x0 + 1);

            const float r = v00 * (1.f - wx) * (1.f - wy)
                          + v01 * wx         * (1.f - wy)
                          + v10 * (1.f - wx) * wy
                          + v11 * wx         * wy;

            bf_split(r, hs[j], ls[j]);
        }
        *reinterpret_cast<ushort4*>(oh + p) = make_ushort4(hs[0], hs[1], hs[2], hs[3]);
        *reinterpret_cast<ushort4*>(ol + p) = make_ushort4(ls[0], ls[1], ls[2], ls[3]);
    }
}

// ======================= launch ============================================
extern "C" void kernel_launch(void* const* d_in, const int* in_sizes, int n_in,
                              void* d_out, int out_size)
{
    const float* x        = (const float*)d_in[0];
    const float* depth_w  = (const float*)d_in[1];
    const float* point_w  = (const float*)d_in[2];
    const float* offset_w = (const float*)d_in[3];
    const float* offset_b = (const float*)d_in[4];
    float* out = (float*)d_out;

    float* offset_p; cudaGetSymbolAddress((void**)&offset_p, g_offset);
    uint32_t* xpk_p; cudaGetSymbolAddress((void**)&xpk_p,    g_xpk);
    unsigned short* shi_p; cudaGetSymbolAddress((void**)&shi_p, g_shi);
    unsigned short* slo_p; cudaGetSymbolAddress((void**)&slo_p, g_slo);
    unsigned short* aoff_p; cudaGetSymbolAddress((void**)&aoff_p, g_Aoffbf);
    unsigned short* apw_p;  cudaGetSymbolAddress((void**)&apw_p,  g_Apwbf);

    cudaFuncSetAttribute(offconv_mma,
                         cudaFuncAttributeMaxDynamicSharedMemorySize, TILE_SMEM);
    cudaFuncSetAttribute(pwconv_mma,
                         cudaFuncAttributeMaxDynamicSharedMemorySize, TILE_SMEM);
    cudaFuncSetAttribute(dwgs_k,
                         cudaFuncAttributeMaxDynamicSharedMemorySize, DWGS_SMEM);

    // 0) fused prep
    prep_k<<<XPK_BLOCKS + WOFF_BLOCKS + WPW_BLOCKS, 256>>>(x, offset_w, point_w);

    // 1) offset conv + bias + tanh
    {
        dim3 g(98 * BB, 2);
        offconv_mma<<<g, 256, TILE_SMEM>>>(aoff_p, xpk_p + GUARD, offset_b, offset_p);
    }

    // 2+3) fused depthwise + grid sample -> split planes
    dwgs_k<<<BB * CC, 1024, DWGS_SMEM>>>(x, depth_w, offset_p, shi_p, slo_p);

    // 4) pointwise 1x1 (bf16-split mma) -> out
    {
        dim3 g(98 * BB, 2);
        pwconv_mma<<<g, 256, TILE_SMEM>>>(apw_p, shi_p, slo_p, out);
    }
}